// round 9
// baseline (speedup 1.0000x reference)
#include <cuda_runtime.h>
#include <cuda_bf16.h>
#include <cstdint>

#define B_    32
#define CIN_  12
#define LEN_  1024
#define TT_   64
#define C1_   64
#define C2_   128

// Scratch (device globals; no runtime allocation)
__device__ float    g_xT[TT_ * B_ * CIN_ * LEN_];   // [t][b][cin][l]
__device__ uint4    g_Apk[7168];     // packed s8 w2 frags [c2h][plane][mi][chunk][lane]
__device__ unsigned g_Alo[2 * 3584]; // lo plane (h=1) words [c2h][koff][c1w][m]
__device__ float2   g_w1pk[84 * 32]; // conv1 weight pairs (read via __ldg, L1-hot)
__device__ float    g_pool[B_ * C2_];

typedef unsigned long long u64;

// ---- packed f32x2 helpers ----
__device__ __forceinline__ u64 pack2(float lo, float hi) {
    u64 r;
    asm("mov.b64 %0, {%1, %2};" : "=l"(r) : "f"(lo), "f"(hi));
    return r;
}
__device__ __forceinline__ void unpack2(u64 v, float& lo, float& hi) {
    asm("mov.b64 {%0, %1}, %2;" : "=f"(lo), "=f"(hi) : "l"(v));
}
__device__ __forceinline__ void ffma2(u64& d, u64 a, u64 b) {
    asm("fma.rn.f32x2 %0, %1, %2, %0;" : "+l"(d) : "l"(a), "l"(b));
}
__device__ __forceinline__ void dp4a(int& acc, unsigned a, unsigned b) {
    asm("dp4a.s32.s32 %0, %1, %2, %0;" : "+r"(acc) : "r"(a), "r"(b));
}
__device__ __forceinline__ void pair_bar(int id) {
    asm volatile("bar.sync %0, 64;" :: "r"(id) : "memory");
}

// ---- warp MMA: m16n8k32 s8.s8.s32 ----
#define IMMA16832(D, A, B0, B1)                                              \
    asm volatile(                                                            \
        "mma.sync.aligned.m16n8k32.row.col.s32.s8.s8.s32 "                   \
        "{%0,%1,%2,%3}, {%4,%5,%6,%7}, {%8,%9}, {%0,%1,%2,%3};"              \
        : "+r"((D)[0]), "+r"((D)[1]), "+r"((D)[2]), "+r"((D)[3])             \
        : "r"((A).x), "r"((A).y), "r"((A).z), "r"((A).w), "r"(B0), "r"(B1))

// ============================================================================
// Kernel A: quantize + pack w2. Exact 2-plane split at scale 2^15.
// ============================================================================
__global__ void __launch_bounds__(256) w2prep_kernel(const float* __restrict__ w2) {
    int idx = blockIdx.x * 256 + threadIdx.x;
    if (idx >= 7168) return;
    {
        int lane = idx & 31;
        int r    = idx >> 5;
        int chunk = r % 14;
        int r2    = r / 14;
        int mi    = r2 & 3;
        int plane = (r2 >> 2) & 1;
        int c2h   = r2 >> 3;
        int g = lane >> 2, c = lane & 3;
        int h = chunk & 1, koff = chunk >> 1;
        int m0 = c2h * 64 + mi * 16;
        int c1b = 32 * h + 4 * c;

        auto pk4 = [&](int m, int c1s) -> unsigned {
            unsigned rr = 0;
#pragma unroll
            for (int j = 0; j < 4; ++j) {
                float w = w2[m * 448 + (c1s + j) * 7 + koff];
                int q = __float2int_rn(w * 32768.f);
                int hi = (q + 128) >> 8;
                int lo = q - (hi << 8);
                int val = plane ? lo : hi;
                rr |= ((unsigned)(val & 0xFF)) << (8 * j);
            }
            return rr;
        };
        uint4 out;
        out.x = pk4(m0 + g,     c1b);
        out.y = pk4(m0 + g + 8, c1b);
        out.z = pk4(m0 + g,     c1b + 16);
        out.w = pk4(m0 + g + 8, c1b + 16);
        g_Apk[idx] = out;
    }
    {
        int c2h  = idx / 3584;
        int rem  = idx % 3584;
        int koff = rem >> 9;
        int c1w  = (rem >> 6) & 7;
        int mloc = rem & 63;
        int m = c2h * 64 + mloc;
        unsigned rr = 0;
#pragma unroll
        for (int j = 0; j < 4; ++j) {
            int c1 = 32 + 4 * c1w + j;
            float w = w2[m * 448 + c1 * 7 + koff];
            int q = __float2int_rn(w * 32768.f);
            int hi = (q + 128) >> 8;
            int lo = q - (hi << 8);
            rr |= ((unsigned)(lo & 0xFF)) << (8 * j);
        }
        g_Alo[idx] = rr;
    }
}

// ============================================================================
// Kernel B: transpose x [b][cin][l][t] -> g_xT [t][b][cin][l]
// ============================================================================
__global__ void __launch_bounds__(256) transpose_kernel(const float* __restrict__ x) {
    __shared__ float tile[32][33];
    const int bc = blockIdx.z;
    const int t0 = blockIdx.x * 32;
    const int l0 = blockIdx.y * 32;
    const int tx = threadIdx.x;
    const int ty = threadIdx.y;
    const float* xb = x + (size_t)bc * LEN_ * TT_;
#pragma unroll
    for (int j = 0; j < 4; ++j)
        tile[ty + j * 8][tx] = xb[(size_t)(l0 + ty + j * 8) * TT_ + t0 + tx];
    __syncthreads();
#pragma unroll
    for (int j = 0; j < 4; ++j)
        g_xT[((size_t)(t0 + ty + j * 8) * (B_ * CIN_) + bc) * LEN_ + l0 + tx] =
            tile[tx][ty + j * 8];
}

// ============================================================================
// Kernel C: pack w1 pairs + zero g_pool
// ============================================================================
__global__ void __launch_bounds__(256) w1prep_kernel(const float* __restrict__ w1) {
    int idx = blockIdx.x * 256 + threadIdx.x;
    if (idx < B_ * C2_) g_pool[idx] = 0.f;
    if (idx < 84 * 32) {
        int r = idx >> 5, i = idx & 31;
        float2 p;
        p.x = w1[(2 * i) * 84 + r];
        p.y = w1[(2 * i + 1) * 84 + r];
        g_w1pk[idx] = p;
    }
}

// ============================================================================
// Kernel D (FUSED, pair-decoupled): each warp-pair (wid 2p, 2p+1) owns a
// private 22-row spike tile + x slice; conv1 computed redundantly per pair;
// NO block-wide barrier in the t-loop — only a 2-warp named barrier per pair.
// Pairs free-run, so tensor/fma/alu phases overlap across warps naturally.
// ============================================================================
#define SPT_PITCH 80
#define SPT_STRIDE 1792                  // 22*80=1760, padded
#define XS_STRIDE  1920                  // 12 cin * 40 floats
#define OFF_SA   0                       // 57344 B
#define OFF_ALO  57344                   // 14336 B
#define OFF_SPT  71680                   // 4 pairs * 2 bufs * 1792 = 14336 B
#define OFF_XS   86016                   // 4 pairs * 2 bufs * 1920 = 15360 B
#define SMEM_SZ  101376
#define APK_U4   3584

extern __shared__ char fsm[];

__global__ void __launch_bounds__(256, 2)
fused_kernel(const float* __restrict__ b1, const float* __restrict__ b2) {
    const int tid  = threadIdx.x;
    const int wid  = tid >> 5;
    const int lane = tid & 31;
    const int wx = wid >> 1;        // 0..3  pair id / N group of 16
    const int wy = wid & 1;         // 0..1  M group of 32
    const int g  = lane >> 2;
    const int c  = lane & 3;
    const int lt  = blockIdx.x;     // 0..15
    const int c2h = blockIdx.y;     // 0..1
    const int b   = blockIdx.z;     // 0..31
    const int l0p = lt * 64 + wx * 16;   // pair's base l

    uint4*    sA   = reinterpret_cast<uint4*>(fsm + OFF_SA);
    unsigned* sAlo = reinterpret_cast<unsigned*>(fsm + OFF_ALO);
    char*  sptP[2] = {fsm + OFF_SPT + (wx * 2 + 0) * SPT_STRIDE,
                      fsm + OFF_SPT + (wx * 2 + 1) * SPT_STRIDE};
    float* xsP[2]  = {reinterpret_cast<float*>(fsm + OFF_XS + (wx * 2 + 0) * XS_STRIDE),
                      reinterpret_cast<float*>(fsm + OFF_XS + (wx * 2 + 1) * XS_STRIDE)};
    const int barid = 1 + wx;
    const int pl = lane + 32 * wy;  // 0..63 within pair

    // ---- one-time block-wide staging ----
    {
        const uint4* gA = g_Apk + c2h * APK_U4;
#pragma unroll 7
        for (int i = tid; i < APK_U4; i += 256) sA[i] = gA[i];
        const unsigned* gL = g_Alo + c2h * 3584;
#pragma unroll 7
        for (int i = tid; i < 3584; i += 256) sAlo[i] = gL[i];
    }

    // pair-private x slice: cols 0..39 <-> l = l0p-8 .. l0p+31; 120 float4
    auto ldg_xs = [&](int t, float4* out2) {
#pragma unroll
        for (int s = 0; s < 2; ++s) {
            int i = pl + 64 * s;
            float4 v = make_float4(0.f, 0.f, 0.f, 0.f);
            if (i < 120 && t < TT_) {
                int cin = i / 10, q = i % 10;
                int l = l0p - 8 + q * 4;
                if (l >= 0 && l + 3 < LEN_)
                    v = *reinterpret_cast<const float4*>(
                        g_xT + ((size_t)((t * B_ + b) * CIN_) + cin) * LEN_ + l);
            }
            out2[s] = v;
        }
    };
    auto sts_xs = [&](const float4* v2, float* buf) {
#pragma unroll
        for (int s = 0; s < 2; ++s) {
            int i = pl + 64 * s;
            if (i < 120) {
                int cin = i / 10, q = i % 10;
                *reinterpret_cast<float4*>(buf + cin * 40 + q * 4) = v2[s];
            }
        }
    };

    const float b1lo = b1[2 * lane];
    const float b1hi = b1[2 * lane + 1];

    // conv1 for this pair's rows: warp computes 11 rows (wy*11 .. wy*11+10),
    // two passes (6 + 5 rows) to bound transient registers.
    auto conv1_step = [&](const float* xsb, char* sptb) {
        const int jj0 = wy * 11;
#pragma unroll 1
        for (int pass = 0; pass < 2; ++pass) {
            const int r0 = pass * 6;
            const int nr = pass ? 5 : 6;
            u64 acc[6];
#pragma unroll
            for (int r = 0; r < 6; ++r) acc[r] = 0ull;
#pragma unroll 1
            for (int cin = 0; cin < 12; ++cin) {
                const float* xr = xsb + cin * 40 + jj0 + r0 + 2;
                u64 pv[12];
#pragma unroll
                for (int m = 0; m < 12; ++m) {
                    float xv = xr[m];
                    pv[m] = pack2(xv, xv);
                }
#pragma unroll
                for (int k = 0; k < 7; ++k) {
                    float2 wp = __ldg(&g_w1pk[(cin * 7 + k) * 32 + lane]);
                    u64 wpk = pack2(wp.x, wp.y);
#pragma unroll
                    for (int r = 0; r < 6; ++r)
                        if (r < nr) ffma2(acc[r], pv[r + k], wpk);
                }
            }
#pragma unroll
            for (int r = 0; r < 6; ++r) {
                if (r < nr) {
                    int jj = jj0 + r0 + r;
                    int l = l0p - 3 + jj;
                    float v0, v1;
                    unpack2(acc[r], v0, v1);
                    bool in = ((unsigned)l < (unsigned)LEN_);
                    unsigned s0 = (in && 2.f * (v0 + b1lo) >= 0.5f) ? 1u : 0u;
                    unsigned s1 = (in && 2.f * (v1 + b1hi) >= 0.5f) ? 1u : 0u;
                    *reinterpret_cast<unsigned short*>(
                        sptb + jj * SPT_PITCH + 2 * lane) =
                        (unsigned short)(s0 | (s1 << 8));
                }
            }
        }
    };

    // ---- prologue: stage x(0), x(1); conv1(0) ----
    {
        float4 v0[2], v1[2];
        ldg_xs(0, v0);
        ldg_xs(1, v1);
        sts_xs(v0, xsP[0]);
        sts_xs(v1, xsP[1]);
    }
    __syncthreads();                 // sA/sAlo + pair xs visible
    conv1_step(xsP[0], sptP[0]);     // spikes for t=0
    pair_bar(barid);                 // partner's spT(0) visible

    float bb[2][2];
#pragma unroll
    for (int mt = 0; mt < 2; ++mt)
#pragma unroll
        for (int hf = 0; hf < 2; ++hf)
            bb[mt][hf] = 2.f * b2[c2h * 64 + wy * 32 + mt * 16 + g + hf * 8];

    float v[2][2][4];
#pragma unroll
    for (int mt = 0; mt < 2; ++mt)
#pragma unroll
        for (int nt = 0; nt < 2; ++nt)
#pragma unroll
            for (int e = 0; e < 4; ++e) v[mt][nt][e] = 0.f;
    float accs[2][2] = {{0.f, 0.f}, {0.f, 0.f}};

    const float SCALE = 6.103515625e-05f;   // 2^-14
    const float INV_TAU = 1.0f / 0.9f;

#pragma unroll 1
    for (int t = 0; t < TT_; ++t) {
        const char* curB = sptP[t & 1];

        float4 stg[2];
        ldg_xs(t + 2, stg);          // early: hides under MMA phase

        int dh[2][2][4], dl[2][2][4], ds[2][2][4];
#pragma unroll
        for (int mt = 0; mt < 2; ++mt)
#pragma unroll
            for (int nt = 0; nt < 2; ++nt)
#pragma unroll
                for (int e = 0; e < 4; ++e) {
                    dh[mt][nt][e] = 0; dl[mt][nt][e] = 0; ds[mt][nt][e] = 0;
                }

        // ---- tensor phase: hi (h0+h1) + lo (h0) = 12 IMMAs per koff ----
#pragma unroll 1
        for (int koff = 0; koff < 7; ++koff) {
            const int ch0 = koff * 2, ch1 = ch0 + 1;
            uint4 ah0[2], ah1[2], al0[2];
#pragma unroll
            for (int mt = 0; mt < 2; ++mt) {
                int mi = wy * 2 + mt;
                ah0[mt] = sA[((0 + mi) * 14 + ch0) * 32 + lane];
                ah1[mt] = sA[((0 + mi) * 14 + ch1) * 32 + lane];
                al0[mt] = sA[((4 + mi) * 14 + ch0) * 32 + lane];
            }
            const char* brow = curB + (size_t)(g + koff) * SPT_PITCH + c * 4;
            unsigned b00[2], b01[2], b10[2], b11[2];
#pragma unroll
            for (int nt = 0; nt < 2; ++nt) {
                const char* p = brow + nt * 8 * SPT_PITCH;
                b00[nt] = *reinterpret_cast<const unsigned*>(p);
                b01[nt] = *reinterpret_cast<const unsigned*>(p + 16);
                b10[nt] = *reinterpret_cast<const unsigned*>(p + 32);
                b11[nt] = *reinterpret_cast<const unsigned*>(p + 48);
            }
#pragma unroll
            for (int nt = 0; nt < 2; ++nt) {
                IMMA16832(dh[0][nt], ah0[0], b00[nt], b01[nt]);
                IMMA16832(dh[1][nt], ah0[1], b00[nt], b01[nt]);
                IMMA16832(dh[0][nt], ah1[0], b10[nt], b11[nt]);
                IMMA16832(dh[1][nt], ah1[1], b10[nt], b11[nt]);
                IMMA16832(dl[0][nt], al0[0], b00[nt], b01[nt]);
                IMMA16832(dl[1][nt], al0[1], b00[nt], b01[nt]);
            }
        }

        // ---- alu phase: lo (h=1) via dp4a ----
#pragma unroll 1
        for (int koff = 0; koff < 7; ++koff) {
            const char* bbase = curB + (size_t)(2 * c + koff) * SPT_PITCH + 32;
            const unsigned* abase = sAlo + koff * 512 + wy * 32 + g;
#pragma unroll
            for (int c1w = 0; c1w < 8; ++c1w) {
                unsigned bw00 = *reinterpret_cast<const unsigned*>(bbase + c1w * 4);
                unsigned bw01 = *reinterpret_cast<const unsigned*>(bbase + c1w * 4 + SPT_PITCH);
                unsigned bw10 = *reinterpret_cast<const unsigned*>(bbase + c1w * 4 + 8 * SPT_PITCH);
                unsigned bw11 = *reinterpret_cast<const unsigned*>(bbase + c1w * 4 + 9 * SPT_PITCH);
                const unsigned* ap = abase + c1w * 64;
                unsigned a00 = ap[0], a01 = ap[8], a10 = ap[16], a11 = ap[24];
                dp4a(ds[0][0][0], a00, bw00); dp4a(ds[0][0][1], a00, bw01);
                dp4a(ds[0][0][2], a01, bw00); dp4a(ds[0][0][3], a01, bw01);
                dp4a(ds[0][1][0], a00, bw10); dp4a(ds[0][1][1], a00, bw11);
                dp4a(ds[0][1][2], a01, bw10); dp4a(ds[0][1][3], a01, bw11);
                dp4a(ds[1][0][0], a10, bw00); dp4a(ds[1][0][1], a10, bw01);
                dp4a(ds[1][0][2], a11, bw00); dp4a(ds[1][0][3], a11, bw01);
                dp4a(ds[1][1][0], a10, bw10); dp4a(ds[1][1][1], a10, bw11);
                dp4a(ds[1][1][2], a11, bw10); dp4a(ds[1][1][3], a11, bw11);
            }
        }

        // ---- fma phase: conv1 for t+1 (pair-private) ----
        if (t + 1 < TT_) conv1_step(xsP[(t + 1) & 1], sptP[(t + 1) & 1]);

        sts_xs(stg, xsP[t & 1]);    // x(t+2) -> buffer parity (t+2)&1 == t&1

        // ---- LIF2: q = (hi<<8) + lo(IMMA h0) + lo(dp4a h1), exact integer ----
#pragma unroll
        for (int mt = 0; mt < 2; ++mt)
#pragma unroll
            for (int nt = 0; nt < 2; ++nt)
#pragma unroll
                for (int e = 0; e < 4; ++e) {
                    int hf = e >> 1;
                    int q = dl[mt][nt][e] + ds[mt][nt][e] + (dh[mt][nt][e] << 8);
                    float hval = fmaf((float)q, SCALE, bb[mt][hf]);
                    float vv = v[mt][nt][e];
                    vv = fmaf(hval - vv, INV_TAU, vv);
                    if (vv >= 0.5f) { accs[mt][hf] += 1.f; vv = 0.f; }
                    v[mt][nt][e] = vv;
                }

        pair_bar(barid);            // 2-warp handoff; pairs stay decoupled
    }

#pragma unroll
    for (int mt = 0; mt < 2; ++mt)
#pragma unroll
        for (int hf = 0; hf < 2; ++hf) {
            int c2 = c2h * 64 + wy * 32 + mt * 16 + g + hf * 8;
            atomicAdd(&g_pool[b * C2_ + c2], accs[mt][hf]);
        }
}

// ============================================================================
// Kernel E: FC
// ============================================================================
__global__ void fc_kernel(const float* __restrict__ fcw,
                          const float* __restrict__ fcb,
                          float* __restrict__ out) {
    const int tid = threadIdx.x;
    if (tid < B_ * 4) {
        int b = tid >> 2, n = tid & 3;
        float s = 0.f;
#pragma unroll 8
        for (int c = 0; c < C2_; ++c)
            s += g_pool[b * C2_ + c] * fcw[n * C2_ + c];
        out[b * 4 + n] = s * (1.f / (float)(TT_ * LEN_)) + fcb[n];
    }
}

// ============================================================================
extern "C" void kernel_launch(void* const* d_in, const int* in_sizes, int n_in,
                              void* d_out, int out_size) {
    const float* x   = (const float*)d_in[0];
    const float* w1  = (const float*)d_in[1];
    const float* b1  = (const float*)d_in[2];
    const float* w2  = (const float*)d_in[3];
    const float* b2  = (const float*)d_in[4];
    const float* fcw = (const float*)d_in[5];
    const float* fcb = (const float*)d_in[6];
    float* out = (float*)d_out;

    cudaFuncSetAttribute(fused_kernel,
                         cudaFuncAttributeMaxDynamicSharedMemorySize, SMEM_SZ);

    w2prep_kernel<<<28, 256>>>(w2);                                             // 1
    transpose_kernel<<<dim3(TT_ / 32, LEN_ / 32, B_ * CIN_), dim3(32, 8)>>>(x); // 2
    w1prep_kernel<<<16, 256>>>(w1);                                             // 3
    fused_kernel<<<dim3(16, 2, B_), 256, SMEM_SZ>>>(b1, b2);                    // 4 <- ncu
    fc_kernel<<<1, 128>>>(fcw, fcb, out);                                       // 5
}

// round 10
// speedup vs baseline: 2.0604x; 2.0604x over previous
#include <cuda_runtime.h>
#include <cuda_bf16.h>
#include <cstdint>

#define B_    32
#define CIN_  12
#define LEN_  1024
#define TT_   64
#define C1_   64
#define C2_   128

// Scratch (device globals; no runtime allocation)
__device__ float    g_xT[TT_ * B_ * CIN_ * LEN_];   // [t][b][cin][l]
__device__ uint4    g_Apk[7168];     // packed s8 w2 frags [c2h][plane][mi][chunk][lane]
__device__ unsigned g_Alo[2 * 3584]; // lo plane (h=1) words [c2h][koff][c1w][m]
__device__ float2   g_w1pk[84 * 32]; // conv1 weight pairs
__device__ float    g_pool[B_ * C2_];

typedef unsigned long long u64;

// ---- packed f32x2 helpers ----
__device__ __forceinline__ u64 pack2(float lo, float hi) {
    u64 r;
    asm("mov.b64 %0, {%1, %2};" : "=l"(r) : "f"(lo), "f"(hi));
    return r;
}
__device__ __forceinline__ void unpack2(u64 v, float& lo, float& hi) {
    asm("mov.b64 {%0, %1}, %2;" : "=f"(lo), "=f"(hi) : "l"(v));
}
__device__ __forceinline__ void ffma2(u64& d, u64 a, u64 b) {
    asm("fma.rn.f32x2 %0, %1, %2, %0;" : "+l"(d) : "l"(a), "l"(b));
}
__device__ __forceinline__ void dp4a(int& acc, unsigned a, unsigned b) {
    asm("dp4a.s32.s32 %0, %1, %2, %0;" : "+r"(acc) : "r"(a), "r"(b));
}

// ---- warp MMA: m16n8k32 s8.s8.s32 ----
#define IMMA16832(D, A, B0, B1)                                              \
    asm volatile(                                                            \
        "mma.sync.aligned.m16n8k32.row.col.s32.s8.s8.s32 "                   \
        "{%0,%1,%2,%3}, {%4,%5,%6,%7}, {%8,%9}, {%0,%1,%2,%3};"              \
        : "+r"((D)[0]), "+r"((D)[1]), "+r"((D)[2]), "+r"((D)[3])             \
        : "r"((A).x), "r"((A).y), "r"((A).z), "r"((A).w), "r"(B0), "r"(B1))

// ============================================================================
// Kernel A: quantize + pack w2. Exact 2-plane split at scale 2^15.
// ============================================================================
__global__ void __launch_bounds__(256) w2prep_kernel(const float* __restrict__ w2) {
    int idx = blockIdx.x * 256 + threadIdx.x;
    if (idx >= 7168) return;
    {
        int lane = idx & 31;
        int r    = idx >> 5;
        int chunk = r % 14;
        int r2    = r / 14;
        int mi    = r2 & 3;
        int plane = (r2 >> 2) & 1;
        int c2h   = r2 >> 3;
        int g = lane >> 2, c = lane & 3;
        int h = chunk & 1, koff = chunk >> 1;
        int m0 = c2h * 64 + mi * 16;
        int c1b = 32 * h + 4 * c;

        auto pk4 = [&](int m, int c1s) -> unsigned {
            unsigned rr = 0;
#pragma unroll
            for (int j = 0; j < 4; ++j) {
                float w = w2[m * 448 + (c1s + j) * 7 + koff];
                int q = __float2int_rn(w * 32768.f);
                int hi = (q + 128) >> 8;
                int lo = q - (hi << 8);
                int val = plane ? lo : hi;
                rr |= ((unsigned)(val & 0xFF)) << (8 * j);
            }
            return rr;
        };
        uint4 out;
        out.x = pk4(m0 + g,     c1b);
        out.y = pk4(m0 + g + 8, c1b);
        out.z = pk4(m0 + g,     c1b + 16);
        out.w = pk4(m0 + g + 8, c1b + 16);
        g_Apk[idx] = out;
    }
    {
        int c2h  = idx / 3584;
        int rem  = idx % 3584;
        int koff = rem >> 9;
        int c1w  = (rem >> 6) & 7;
        int mloc = rem & 63;
        int m = c2h * 64 + mloc;
        unsigned rr = 0;
#pragma unroll
        for (int j = 0; j < 4; ++j) {
            int c1 = 32 + 4 * c1w + j;
            float w = w2[m * 448 + c1 * 7 + koff];
            int q = __float2int_rn(w * 32768.f);
            int hi = (q + 128) >> 8;
            int lo = q - (hi << 8);
            rr |= ((unsigned)(lo & 0xFF)) << (8 * j);
        }
        g_Alo[idx] = rr;
    }
}

// ============================================================================
// Kernel B: transpose x [b][cin][l][t] -> g_xT [t][b][cin][l]
// ============================================================================
__global__ void __launch_bounds__(256) transpose_kernel(const float* __restrict__ x) {
    __shared__ float tile[32][33];
    const int bc = blockIdx.z;
    const int t0 = blockIdx.x * 32;
    const int l0 = blockIdx.y * 32;
    const int tx = threadIdx.x;
    const int ty = threadIdx.y;
    const float* xb = x + (size_t)bc * LEN_ * TT_;
#pragma unroll
    for (int j = 0; j < 4; ++j)
        tile[ty + j * 8][tx] = xb[(size_t)(l0 + ty + j * 8) * TT_ + t0 + tx];
    __syncthreads();
#pragma unroll
    for (int j = 0; j < 4; ++j)
        g_xT[((size_t)(t0 + ty + j * 8) * (B_ * CIN_) + bc) * LEN_ + l0 + tx] =
            tile[tx][ty + j * 8];
}

// ============================================================================
// Kernel C: pack w1 pairs + zero g_pool
// ============================================================================
__global__ void __launch_bounds__(256) w1prep_kernel(const float* __restrict__ w1) {
    int idx = blockIdx.x * 256 + threadIdx.x;
    if (idx < B_ * C2_) g_pool[idx] = 0.f;
    if (idx < 84 * 32) {
        int r = idx >> 5, i = idx & 31;
        float2 p;
        p.x = w1[(2 * i) * 84 + r];
        p.y = w1[(2 * i + 1) * 84 + r];
        g_w1pk[idx] = p;
    }
}

// ============================================================================
// Kernel D (FUSED, r7 base + fine-grained interleave): single koff loop per
// timestep issues 12 IMMAs + 16 dp4a-groups + 2 cin-chunks of conv1, so each
// warp's own instruction stream alternates tensor/alu/fma pipes at ~dozen-
// instruction granularity. Accumulation orders identical to r7.
// ============================================================================
#define SPT_PITCH 80
#define OFF_SA   0                       //  57344 B  IMMA A frags
#define OFF_ALO  57344                   //  14336 B  dp4a lo words
#define OFF_SPT0 (OFF_ALO + 14336)       //   5760 B
#define OFF_SPT1 (OFF_SPT0 + 5760)       //   5760 B
#define OFF_XS0  (OFF_SPT1 + 5760)       //   3840 B
#define OFF_XS1  (OFF_XS0 + 3840)        //   3840 B
#define OFF_WS1  (OFF_XS1 + 3840)        //  21504 B
#define SMEM_SZ  (OFF_WS1 + 21504)       // 112384 B
#define APK_U4   3584

extern __shared__ char fsm[];

__global__ void __launch_bounds__(256, 2)
fused_kernel(const float* __restrict__ b1, const float* __restrict__ b2) {
    const int tid  = threadIdx.x;
    const int wid  = tid >> 5;
    const int lane = tid & 31;
    const int wy = wid >> 2;        // 0..1  M group of 32
    const int wx = wid & 3;         // 0..3  N group of 16
    const int g  = lane >> 2;
    const int c  = lane & 3;
    const int lt  = blockIdx.x;     // 0..15
    const int c2h = blockIdx.y;     // 0..1
    const int b   = blockIdx.z;     // 0..31
    const int l0  = lt * 64;

    uint4*    sA   = reinterpret_cast<uint4*>(fsm + OFF_SA);
    unsigned* sAlo = reinterpret_cast<unsigned*>(fsm + OFF_ALO);
    char*     spt[2] = {fsm + OFF_SPT0, fsm + OFF_SPT1};
    float*    xs[2]  = {reinterpret_cast<float*>(fsm + OFF_XS0),
                        reinterpret_cast<float*>(fsm + OFF_XS1)};
    float2*   ws1 = reinterpret_cast<float2*>(fsm + OFF_WS1);

    // ---- one-time staging ----
    {
        const uint4* gA = g_Apk + c2h * APK_U4;
#pragma unroll 7
        for (int i = tid; i < APK_U4; i += 256) sA[i] = gA[i];
        const unsigned* gL = g_Alo + c2h * 3584;
#pragma unroll 7
        for (int i = tid; i < 3584; i += 256) sAlo[i] = gL[i];
#pragma unroll 2
        for (int i = tid; i < 84 * 32; i += 256) ws1[i] = g_w1pk[i];
    }

    auto ldg_xs = [&](int t) -> float4 {
        float4 v = make_float4(0.f, 0.f, 0.f, 0.f);
        if (tid < 240 && t < TT_) {
            int cin = tid / 20, q = tid % 20;
            int l = l0 - 8 + q * 4;
            if (l >= 0 && l + 3 < LEN_) {
                v = *reinterpret_cast<const float4*>(
                    g_xT + ((size_t)((t * B_ + b) * CIN_) + cin) * LEN_ + l);
            }
        }
        return v;
    };
    auto sts_xs = [&](float4 v, float* buf) {
        if (tid < 240) {
            int cin = tid / 20, q = tid % 20;
            *reinterpret_cast<float4*>(buf + cin * 80 + q * 4) = v;
        }
    };

    float4 st0 = ldg_xs(0);
    sts_xs(st0, xs[0]);

    const float b1lo = b1[2 * lane];
    const float b1hi = b1[2 * lane + 1];
    const int   jb   = wid * 9;

    // full conv1 step (prologue only)
    auto conv1_step = [&](const float* xsb, char* sptb) {
        u64 acc[9];
#pragma unroll
        for (int r = 0; r < 9; ++r) acc[r] = 0ull;
#pragma unroll 1
        for (int cin = 0; cin < 12; ++cin) {
            const float* xr = xsb + cin * 80 + jb + 2;
            u64 pv[15];
#pragma unroll
            for (int m = 0; m < 15; ++m) {
                float xv = xr[m];
                pv[m] = pack2(xv, xv);
            }
#pragma unroll
            for (int k = 0; k < 7; ++k) {
                float2 wp = ws1[(cin * 7 + k) * 32 + lane];
                u64 wpk = pack2(wp.x, wp.y);
#pragma unroll
                for (int r = 0; r < 9; ++r)
                    ffma2(acc[r], pv[r + k], wpk);
            }
        }
#pragma unroll
        for (int r = 0; r < 9; ++r) {
            int j = jb + r;
            int l = l0 - 3 + j;
            float v0, v1;
            unpack2(acc[r], v0, v1);
            bool in = ((unsigned)l < (unsigned)LEN_);
            unsigned s0 = (in && 2.f * (v0 + b1lo) >= 0.5f) ? 1u : 0u;
            unsigned s1 = (in && 2.f * (v1 + b1hi) >= 0.5f) ? 1u : 0u;
            *reinterpret_cast<unsigned short*>(sptb + j * SPT_PITCH + 2 * lane) =
                (unsigned short)(s0 | (s1 << 8));
        }
    };

    __syncthreads();            // staging + xs(0) visible
    conv1_step(xs[0], spt[0]);  // spikes for t=0
    float4 st1 = ldg_xs(1);
    sts_xs(st1, xs[1]);
    __syncthreads();            // spT(0) + xs(1) visible

    float bb[2][2];
#pragma unroll
    for (int mt = 0; mt < 2; ++mt)
#pragma unroll
        for (int hf = 0; hf < 2; ++hf)
            bb[mt][hf] = 2.f * b2[c2h * 64 + wy * 32 + mt * 16 + g + hf * 8];

    float v[2][2][4];
#pragma unroll
    for (int mt = 0; mt < 2; ++mt)
#pragma unroll
        for (int nt = 0; nt < 2; ++nt)
#pragma unroll
            for (int e = 0; e < 4; ++e) v[mt][nt][e] = 0.f;
    float accs[2][2] = {{0.f, 0.f}, {0.f, 0.f}};

    const float SCALE = 6.103515625e-05f;   // 2^-14
    const float INV_TAU = 1.0f / 0.9f;

#pragma unroll 1
    for (int t = 0; t < TT_; ++t) {
        const char* curB = spt[t & 1];
        const bool  doc1 = (t + 1 < TT_);
        const float* xnb = xs[(t + 1) & 1];
        char*        sptn = spt[(t + 1) & 1];

        float4 stg = ldg_xs(t + 2);   // early: hides under compute

        int dh[2][2][4], dl[2][2][4], ds[2][2][4];
#pragma unroll
        for (int mt = 0; mt < 2; ++mt)
#pragma unroll
            for (int nt = 0; nt < 2; ++nt)
#pragma unroll
                for (int e = 0; e < 4; ++e) {
                    dh[mt][nt][e] = 0; dl[mt][nt][e] = 0; ds[mt][nt][e] = 0;
                }
        u64 c1acc[9];
#pragma unroll
        for (int r = 0; r < 9; ++r) c1acc[r] = 0ull;

        // ==== merged koff loop: tensor + alu + fma interleaved ====
#pragma unroll 1
        for (int koff = 0; koff < 7; ++koff) {
            // ---- tensor: 12 IMMAs (hi h0+h1, lo h0) ----
            const int ch0 = koff * 2, ch1 = ch0 + 1;
            uint4 ah0[2], ah1[2], al0[2];
#pragma unroll
            for (int mt = 0; mt < 2; ++mt) {
                int mi = wy * 2 + mt;
                ah0[mt] = sA[((0 + mi) * 14 + ch0) * 32 + lane];
                ah1[mt] = sA[((0 + mi) * 14 + ch1) * 32 + lane];
                al0[mt] = sA[((4 + mi) * 14 + ch0) * 32 + lane];
            }
            const char* brow = curB + (size_t)(wx * 16 + g + koff) * SPT_PITCH + c * 4;
            unsigned b00[2], b01[2], b10[2], b11[2];
#pragma unroll
            for (int nt = 0; nt < 2; ++nt) {
                const char* p = brow + nt * 8 * SPT_PITCH;
                b00[nt] = *reinterpret_cast<const unsigned*>(p);
                b01[nt] = *reinterpret_cast<const unsigned*>(p + 16);
                b10[nt] = *reinterpret_cast<const unsigned*>(p + 32);
                b11[nt] = *reinterpret_cast<const unsigned*>(p + 48);
            }
#pragma unroll
            for (int nt = 0; nt < 2; ++nt) {
                IMMA16832(dh[0][nt], ah0[0], b00[nt], b01[nt]);
                IMMA16832(dh[1][nt], ah0[1], b00[nt], b01[nt]);
                IMMA16832(dh[0][nt], ah1[0], b10[nt], b11[nt]);
                IMMA16832(dh[1][nt], ah1[1], b10[nt], b11[nt]);
                IMMA16832(dl[0][nt], al0[0], b00[nt], b01[nt]);
                IMMA16832(dl[1][nt], al0[1], b00[nt], b01[nt]);
            }

            // ---- alu: 16 dp4a groups (lo h=1) ----
            {
                const char* bbase = curB + (size_t)(wx * 16 + 2 * c + koff) * SPT_PITCH + 32;
                const unsigned* abase = sAlo + koff * 512 + wy * 32 + g;
#pragma unroll
                for (int c1w = 0; c1w < 8; ++c1w) {
                    unsigned bw00 = *reinterpret_cast<const unsigned*>(bbase + c1w * 4);
                    unsigned bw01 = *reinterpret_cast<const unsigned*>(bbase + c1w * 4 + SPT_PITCH);
                    unsigned bw10 = *reinterpret_cast<const unsigned*>(bbase + c1w * 4 + 8 * SPT_PITCH);
                    unsigned bw11 = *reinterpret_cast<const unsigned*>(bbase + c1w * 4 + 9 * SPT_PITCH);
                    const unsigned* ap = abase + c1w * 64;
                    unsigned a00 = ap[0], a01 = ap[8], a10 = ap[16], a11 = ap[24];
                    dp4a(ds[0][0][0], a00, bw00); dp4a(ds[0][0][1], a00, bw01);
                    dp4a(ds[0][0][2], a01, bw00); dp4a(ds[0][0][3], a01, bw01);
                    dp4a(ds[0][1][0], a00, bw10); dp4a(ds[0][1][1], a00, bw11);
                    dp4a(ds[0][1][2], a01, bw10); dp4a(ds[0][1][3], a01, bw11);
                    dp4a(ds[1][0][0], a10, bw00); dp4a(ds[1][0][1], a10, bw01);
                    dp4a(ds[1][0][2], a11, bw00); dp4a(ds[1][0][3], a11, bw01);
                    dp4a(ds[1][1][0], a10, bw10); dp4a(ds[1][1][1], a10, bw11);
                    dp4a(ds[1][1][2], a11, bw10); dp4a(ds[1][1][3], a11, bw11);
                }
            }

            // ---- fma: conv1(t+1) chunk, cin = {2*koff, 2*koff+1} ----
            if (doc1 && koff < 6) {
#pragma unroll
                for (int ci = 0; ci < 2; ++ci) {
                    const int cin = 2 * koff + ci;
                    const float* xr = xnb + cin * 80 + jb + 2;
                    u64 pv[15];
#pragma unroll
                    for (int m = 0; m < 15; ++m) {
                        float xv = xr[m];
                        pv[m] = pack2(xv, xv);
                    }
#pragma unroll
                    for (int k = 0; k < 7; ++k) {
                        float2 wp = ws1[(cin * 7 + k) * 32 + lane];
                        u64 wpk = pack2(wp.x, wp.y);
#pragma unroll
                        for (int r = 0; r < 9; ++r)
                            ffma2(c1acc[r], pv[r + k], wpk);
                    }
                }
            }
        }

        // ---- spike store for t+1 ----
        if (doc1) {
#pragma unroll
            for (int r = 0; r < 9; ++r) {
                int j = jb + r;
                int l = l0 - 3 + j;
                float v0, v1;
                unpack2(c1acc[r], v0, v1);
                bool in = ((unsigned)l < (unsigned)LEN_);
                unsigned s0 = (in && 2.f * (v0 + b1lo) >= 0.5f) ? 1u : 0u;
                unsigned s1 = (in && 2.f * (v1 + b1hi) >= 0.5f) ? 1u : 0u;
                *reinterpret_cast<unsigned short*>(sptn + j * SPT_PITCH + 2 * lane) =
                    (unsigned short)(s0 | (s1 << 8));
            }
        }

        sts_xs(stg, xs[t & 1]);

        // ---- LIF2: q = (hi<<8) + lo(IMMA h0) + lo(dp4a h1), exact integer ----
#pragma unroll
        for (int mt = 0; mt < 2; ++mt)
#pragma unroll
            for (int nt = 0; nt < 2; ++nt)
#pragma unroll
                for (int e = 0; e < 4; ++e) {
                    int hf = e >> 1;
                    int q = dl[mt][nt][e] + ds[mt][nt][e] + (dh[mt][nt][e] << 8);
                    float hval = fmaf((float)q, SCALE, bb[mt][hf]);
                    float vv = v[mt][nt][e];
                    vv = fmaf(hval - vv, INV_TAU, vv);
                    if (vv >= 0.5f) { accs[mt][hf] += 1.f; vv = 0.f; }
                    v[mt][nt][e] = vv;
                }

        __syncthreads();
    }

#pragma unroll
    for (int mt = 0; mt < 2; ++mt)
#pragma unroll
        for (int hf = 0; hf < 2; ++hf) {
            int c2 = c2h * 64 + wy * 32 + mt * 16 + g + hf * 8;
            atomicAdd(&g_pool[b * C2_ + c2], accs[mt][hf]);
        }
}

// ============================================================================
// Kernel E: FC
// ============================================================================
__global__ void fc_kernel(const float* __restrict__ fcw,
                          const float* __restrict__ fcb,
                          float* __restrict__ out) {
    const int tid = threadIdx.x;
    if (tid < B_ * 4) {
        int b = tid >> 2, n = tid & 3;
        float s = 0.f;
#pragma unroll 8
        for (int c = 0; c < C2_; ++c)
            s += g_pool[b * C2_ + c] * fcw[n * C2_ + c];
        out[b * 4 + n] = s * (1.f / (float)(TT_ * LEN_)) + fcb[n];
    }
}

// ============================================================================
extern "C" void kernel_launch(void* const* d_in, const int* in_sizes, int n_in,
                              void* d_out, int out_size) {
    const float* x   = (const float*)d_in[0];
    const float* w1  = (const float*)d_in[1];
    const float* b1  = (const float*)d_in[2];
    const float* w2  = (const float*)d_in[3];
    const float* b2  = (const float*)d_in[4];
    const float* fcw = (const float*)d_in[5];
    const float* fcb = (const float*)d_in[6];
    float* out = (float*)d_out;

    cudaFuncSetAttribute(fused_kernel,
                         cudaFuncAttributeMaxDynamicSharedMemorySize, SMEM_SZ);

    w2prep_kernel<<<28, 256>>>(w2);                                             // 1
    transpose_kernel<<<dim3(TT_ / 32, LEN_ / 32, B_ * CIN_), dim3(32, 8)>>>(x); // 2
    w1prep_kernel<<<16, 256>>>(w1);                                             // 3
    fused_kernel<<<dim3(16, 2, B_), 256, SMEM_SZ>>>(b1, b2);                    // 4 <- ncu
    fc_kernel<<<1, 128>>>(fcw, fcb, out);                                       // 5
}

// round 11
// speedup vs baseline: 2.1200x; 1.0289x over previous
#include <cuda_runtime.h>
#include <cuda_bf16.h>
#include <cstdint>

#define B_    32
#define CIN_  12
#define LEN_  1024
#define TT_   64
#define C1_   64
#define C2_   128

// Scratch (device globals; no runtime allocation)
__device__ float    g_xT[TT_ * B_ * CIN_ * LEN_];   // [t][b][cin][l]
__device__ uint4    g_Apk[7168];     // packed s8 w2 frags [c2h][plane][mi][chunk][lane]
__device__ uint4    g_Alo4[2 * 896]; // lo plane (h=1) frag-vectors [c2h][koff][c1w][wy][g]
__device__ float2   g_w1pk[84 * 32]; // conv1 weight pairs
__device__ float    g_pool[B_ * C2_];

typedef unsigned long long u64;

// ---- packed f32x2 helpers ----
__device__ __forceinline__ u64 pack2(float lo, float hi) {
    u64 r;
    asm("mov.b64 %0, {%1, %2};" : "=l"(r) : "f"(lo), "f"(hi));
    return r;
}
__device__ __forceinline__ void unpack2(u64 v, float& lo, float& hi) {
    asm("mov.b64 {%0, %1}, %2;" : "=f"(lo), "=f"(hi) : "l"(v));
}
__device__ __forceinline__ void ffma2(u64& d, u64 a, u64 b) {
    asm("fma.rn.f32x2 %0, %1, %2, %0;" : "+l"(d) : "l"(a), "l"(b));
}
__device__ __forceinline__ void dp4a(int& acc, unsigned a, unsigned b) {
    asm("dp4a.s32.s32 %0, %1, %2, %0;" : "+r"(acc) : "r"(a), "r"(b));
}

// ---- warp MMA: m16n8k32 s8.s8.s32 ----
#define IMMA16832(D, A, B0, B1)                                              \
    asm volatile(                                                            \
        "mma.sync.aligned.m16n8k32.row.col.s32.s8.s8.s32 "                   \
        "{%0,%1,%2,%3}, {%4,%5,%6,%7}, {%8,%9}, {%0,%1,%2,%3};"              \
        : "+r"((D)[0]), "+r"((D)[1]), "+r"((D)[2]), "+r"((D)[3])             \
        : "r"((A).x), "r"((A).y), "r"((A).z), "r"((A).w), "r"(B0), "r"(B1))

// ============================================================================
// Kernel A: quantize + pack w2. Exact 2-plane split at scale 2^15:
// q = round(w*2^15); hi = (q+128)>>8; lo = q - hi*256 (both s8, q = hi*256+lo).
// Outputs: g_Apk (IMMA frags) and g_Alo4 (vectorized h=1 lo frags for dp4a).
// ============================================================================
__global__ void __launch_bounds__(256) w2prep_kernel(const float* __restrict__ w2) {
    int idx = blockIdx.x * 256 + threadIdx.x;
    if (idx >= 7168) return;

    auto lo_of = [&](int m, int c1, int koff) -> int {
        float w = w2[m * 448 + c1 * 7 + koff];
        int q = __float2int_rn(w * 32768.f);
        int hi = (q + 128) >> 8;
        return q - (hi << 8);
    };

    // ---- IMMA fragment packing (unchanged) ----
    {
        int lane = idx & 31;
        int r    = idx >> 5;
        int chunk = r % 14;
        int r2    = r / 14;
        int mi    = r2 & 3;
        int plane = (r2 >> 2) & 1;
        int c2h   = r2 >> 3;
        int g = lane >> 2, c = lane & 3;
        int h = chunk & 1, koff = chunk >> 1;
        int m0 = c2h * 64 + mi * 16;
        int c1b = 32 * h + 4 * c;

        auto pk4 = [&](int m, int c1s) -> unsigned {
            unsigned rr = 0;
#pragma unroll
            for (int j = 0; j < 4; ++j) {
                float w = w2[m * 448 + (c1s + j) * 7 + koff];
                int q = __float2int_rn(w * 32768.f);
                int hi = (q + 128) >> 8;
                int lo = q - (hi << 8);
                int val = plane ? lo : hi;
                rr |= ((unsigned)(val & 0xFF)) << (8 * j);
            }
            return rr;
        };
        uint4 out;
        out.x = pk4(m0 + g,     c1b);
        out.y = pk4(m0 + g + 8, c1b);
        out.z = pk4(m0 + g,     c1b + 16);
        out.w = pk4(m0 + g + 8, c1b + 16);
        g_Apk[idx] = out;
    }

    // ---- dp4a lo fragment vectors (h=1: c1 in [32,64)), uint4 layout ----
    if (idx < 1792) {
        int g    = idx & 7;
        int wy   = (idx >> 3) & 1;
        int c1w  = (idx >> 4) & 7;
        int kk   = idx >> 7;            // c2h*7 + koff
        int koff = kk % 7;
        int c2h  = kk / 7;
        unsigned w4[4];
#pragma unroll
        for (int j = 0; j < 4; ++j) {
            int m = c2h * 64 + wy * 32 + g + 8 * j;
            unsigned rr = 0;
#pragma unroll
            for (int jj = 0; jj < 4; ++jj) {
                int lo = lo_of(m, 32 + 4 * c1w + jj, koff);
                rr |= ((unsigned)(lo & 0xFF)) << (8 * jj);
            }
            w4[j] = rr;
        }
        g_Alo4[idx] = make_uint4(w4[0], w4[1], w4[2], w4[3]);
    }
}

// ============================================================================
// Kernel B: transpose x [b][cin][l][t] -> g_xT [t][b][cin][l]
// ============================================================================
__global__ void __launch_bounds__(256) transpose_kernel(const float* __restrict__ x) {
    __shared__ float tile[32][33];
    const int bc = blockIdx.z;
    const int t0 = blockIdx.x * 32;
    const int l0 = blockIdx.y * 32;
    const int tx = threadIdx.x;
    const int ty = threadIdx.y;
    const float* xb = x + (size_t)bc * LEN_ * TT_;
#pragma unroll
    for (int j = 0; j < 4; ++j)
        tile[ty + j * 8][tx] = xb[(size_t)(l0 + ty + j * 8) * TT_ + t0 + tx];
    __syncthreads();
#pragma unroll
    for (int j = 0; j < 4; ++j)
        g_xT[((size_t)(t0 + ty + j * 8) * (B_ * CIN_) + bc) * LEN_ + l0 + tx] =
            tile[tx][ty + j * 8];
}

// ============================================================================
// Kernel C: pack w1 pairs + zero g_pool
// ============================================================================
__global__ void __launch_bounds__(256) w1prep_kernel(const float* __restrict__ w1) {
    int idx = blockIdx.x * 256 + threadIdx.x;
    if (idx < B_ * C2_) g_pool[idx] = 0.f;
    if (idx < 84 * 32) {
        int r = idx >> 5, i = idx & 31;
        float2 p;
        p.x = w1[(2 * i) * 84 + r];
        p.y = w1[(2 * i + 1) * 84 + r];
        g_w1pk[idx] = p;
    }
}

// ============================================================================
// Kernel D (FUSED, r10 base + dp4a load diet): single koff loop per timestep
// issues 12 IMMAs + dp4a block (now LDS.128-fed) + 2 cin-chunks of conv1.
// All integer sums exact -> rel_err bit-identical to r10.
// ============================================================================
#define SPT_PITCH 80
#define OFF_SA   0                       //  57344 B  IMMA A frags
#define OFF_ALO  57344                   //  14336 B  dp4a lo frag vectors
#define OFF_SPT0 (OFF_ALO + 14336)       //   5760 B
#define OFF_SPT1 (OFF_SPT0 + 5760)       //   5760 B
#define OFF_XS0  (OFF_SPT1 + 5760)       //   3840 B
#define OFF_XS1  (OFF_XS0 + 3840)        //   3840 B
#define OFF_WS1  (OFF_XS1 + 3840)        //  21504 B
#define SMEM_SZ  (OFF_WS1 + 21504)       // 112384 B
#define APK_U4   3584

extern __shared__ char fsm[];

__global__ void __launch_bounds__(256, 2)
fused_kernel(const float* __restrict__ b1, const float* __restrict__ b2) {
    const int tid  = threadIdx.x;
    const int wid  = tid >> 5;
    const int lane = tid & 31;
    const int wy = wid >> 2;        // 0..1  M group of 32
    const int wx = wid & 3;         // 0..3  N group of 16
    const int g  = lane >> 2;
    const int c  = lane & 3;
    const int lt  = blockIdx.x;     // 0..15
    const int c2h = blockIdx.y;     // 0..1
    const int b   = blockIdx.z;     // 0..31
    const int l0  = lt * 64;

    uint4*    sA    = reinterpret_cast<uint4*>(fsm + OFF_SA);
    uint4*    sAlo4 = reinterpret_cast<uint4*>(fsm + OFF_ALO);
    char*     spt[2] = {fsm + OFF_SPT0, fsm + OFF_SPT1};
    float*    xs[2]  = {reinterpret_cast<float*>(fsm + OFF_XS0),
                        reinterpret_cast<float*>(fsm + OFF_XS1)};
    float2*   ws1 = reinterpret_cast<float2*>(fsm + OFF_WS1);

    // ---- one-time staging ----
    {
        const uint4* gA = g_Apk + c2h * APK_U4;
#pragma unroll 7
        for (int i = tid; i < APK_U4; i += 256) sA[i] = gA[i];
        const uint4* gL = g_Alo4 + c2h * 896;
#pragma unroll 2
        for (int i = tid; i < 896; i += 256) sAlo4[i] = gL[i];
#pragma unroll 2
        for (int i = tid; i < 84 * 32; i += 256) ws1[i] = g_w1pk[i];
    }

    auto ldg_xs = [&](int t) -> float4 {
        float4 v = make_float4(0.f, 0.f, 0.f, 0.f);
        if (tid < 240 && t < TT_) {
            int cin = tid / 20, q = tid % 20;
            int l = l0 - 8 + q * 4;
            if (l >= 0 && l + 3 < LEN_) {
                v = *reinterpret_cast<const float4*>(
                    g_xT + ((size_t)((t * B_ + b) * CIN_) + cin) * LEN_ + l);
            }
        }
        return v;
    };
    auto sts_xs = [&](float4 v, float* buf) {
        if (tid < 240) {
            int cin = tid / 20, q = tid % 20;
            *reinterpret_cast<float4*>(buf + cin * 80 + q * 4) = v;
        }
    };

    float4 st0 = ldg_xs(0);
    sts_xs(st0, xs[0]);

    const float b1lo = b1[2 * lane];
    const float b1hi = b1[2 * lane + 1];
    const int   jb   = wid * 9;

    // full conv1 step (prologue only)
    auto conv1_step = [&](const float* xsb, char* sptb) {
        u64 acc[9];
#pragma unroll
        for (int r = 0; r < 9; ++r) acc[r] = 0ull;
#pragma unroll 1
        for (int cin = 0; cin < 12; ++cin) {
            const float* xr = xsb + cin * 80 + jb + 2;
            u64 pv[15];
#pragma unroll
            for (int m = 0; m < 15; ++m) {
                float xv = xr[m];
                pv[m] = pack2(xv, xv);
            }
#pragma unroll
            for (int k = 0; k < 7; ++k) {
                float2 wp = ws1[(cin * 7 + k) * 32 + lane];
                u64 wpk = pack2(wp.x, wp.y);
#pragma unroll
                for (int r = 0; r < 9; ++r)
                    ffma2(acc[r], pv[r + k], wpk);
            }
        }
#pragma unroll
        for (int r = 0; r < 9; ++r) {
            int j = jb + r;
            int l = l0 - 3 + j;
            float v0, v1;
            unpack2(acc[r], v0, v1);
            bool in = ((unsigned)l < (unsigned)LEN_);
            unsigned s0 = (in && 2.f * (v0 + b1lo) >= 0.5f) ? 1u : 0u;
            unsigned s1 = (in && 2.f * (v1 + b1hi) >= 0.5f) ? 1u : 0u;
            *reinterpret_cast<unsigned short*>(sptb + j * SPT_PITCH + 2 * lane) =
                (unsigned short)(s0 | (s1 << 8));
        }
    };

    __syncthreads();            // staging + xs(0) visible
    conv1_step(xs[0], spt[0]);  // spikes for t=0
    float4 st1 = ldg_xs(1);
    sts_xs(st1, xs[1]);
    __syncthreads();            // spT(0) + xs(1) visible

    float bb[2][2];
#pragma unroll
    for (int mt = 0; mt < 2; ++mt)
#pragma unroll
        for (int hf = 0; hf < 2; ++hf)
            bb[mt][hf] = 2.f * b2[c2h * 64 + wy * 32 + mt * 16 + g + hf * 8];

    float v[2][2][4];
#pragma unroll
    for (int mt = 0; mt < 2; ++mt)
#pragma unroll
        for (int nt = 0; nt < 2; ++nt)
#pragma unroll
            for (int e = 0; e < 4; ++e) v[mt][nt][e] = 0.f;
    float accs[2][2] = {{0.f, 0.f}, {0.f, 0.f}};

    const float SCALE = 6.103515625e-05f;   // 2^-14
    const float INV_TAU = 1.0f / 0.9f;

#pragma unroll 1
    for (int t = 0; t < TT_; ++t) {
        const char* curB = spt[t & 1];
        const bool  doc1 = (t + 1 < TT_);
        const float* xnb = xs[(t + 1) & 1];
        char*        sptn = spt[(t + 1) & 1];

        float4 stg = ldg_xs(t + 2);   // early: hides under compute

        int dh[2][2][4], dl[2][2][4], ds[2][2][4];
#pragma unroll
        for (int mt = 0; mt < 2; ++mt)
#pragma unroll
            for (int nt = 0; nt < 2; ++nt)
#pragma unroll
                for (int e = 0; e < 4; ++e) {
                    dh[mt][nt][e] = 0; dl[mt][nt][e] = 0; ds[mt][nt][e] = 0;
                }
        u64 c1acc[9];
#pragma unroll
        for (int r = 0; r < 9; ++r) c1acc[r] = 0ull;

        // ==== merged koff loop: tensor + alu + fma interleaved ====
#pragma unroll 1
        for (int koff = 0; koff < 7; ++koff) {
            // ---- tensor: 12 IMMAs (hi h0+h1, lo h0) ----
            const int ch0 = koff * 2, ch1 = ch0 + 1;
            uint4 ah0[2], ah1[2], al0[2];
#pragma unroll
            for (int mt = 0; mt < 2; ++mt) {
                int mi = wy * 2 + mt;
                ah0[mt] = sA[((0 + mi) * 14 + ch0) * 32 + lane];
                ah1[mt] = sA[((0 + mi) * 14 + ch1) * 32 + lane];
                al0[mt] = sA[((4 + mi) * 14 + ch0) * 32 + lane];
            }
            const char* brow = curB + (size_t)(wx * 16 + g + koff) * SPT_PITCH + c * 4;
            unsigned b00[2], b01[2], b10[2], b11[2];
#pragma unroll
            for (int nt = 0; nt < 2; ++nt) {
                const char* p = brow + nt * 8 * SPT_PITCH;
                b00[nt] = *reinterpret_cast<const unsigned*>(p);
                b01[nt] = *reinterpret_cast<const unsigned*>(p + 16);
                b10[nt] = *reinterpret_cast<const unsigned*>(p + 32);
                b11[nt] = *reinterpret_cast<const unsigned*>(p + 48);
            }
#pragma unroll
            for (int nt = 0; nt < 2; ++nt) {
                IMMA16832(dh[0][nt], ah0[0], b00[nt], b01[nt]);
                IMMA16832(dh[1][nt], ah0[1], b00[nt], b01[nt]);
                IMMA16832(dh[0][nt], ah1[0], b10[nt], b11[nt]);
                IMMA16832(dh[1][nt], ah1[1], b10[nt], b11[nt]);
                IMMA16832(dl[0][nt], al0[0], b00[nt], b01[nt]);
                IMMA16832(dl[1][nt], al0[1], b00[nt], b01[nt]);
            }

            // ---- alu: dp4a (lo h=1), vectorized LDS.128 feeds ----
            {
                const char* rowb = curB + (size_t)(wx * 16 + 2 * c + koff) * SPT_PITCH + 32;
                const uint4* a4p = sAlo4 + koff * 128 + wy * 8 + g;
#pragma unroll
                for (int half = 0; half < 2; ++half) {
                    const int off = half * 16;
                    uint4 r0v = *reinterpret_cast<const uint4*>(rowb + off);
                    uint4 r1v = *reinterpret_cast<const uint4*>(rowb + SPT_PITCH + off);
                    uint4 r8v = *reinterpret_cast<const uint4*>(rowb + 8 * SPT_PITCH + off);
                    uint4 r9v = *reinterpret_cast<const uint4*>(rowb + 9 * SPT_PITCH + off);
                    unsigned w0[4] = {r0v.x, r0v.y, r0v.z, r0v.w};
                    unsigned w1v[4] = {r1v.x, r1v.y, r1v.z, r1v.w};
                    unsigned w8[4] = {r8v.x, r8v.y, r8v.z, r8v.w};
                    unsigned w9[4] = {r9v.x, r9v.y, r9v.z, r9v.w};
#pragma unroll
                    for (int cw = 0; cw < 4; ++cw) {
                        const int c1w = half * 4 + cw;
                        uint4 a4 = a4p[c1w * 16];
                        unsigned bw00 = w0[cw], bw01 = w1v[cw];
                        unsigned bw10 = w8[cw], bw11 = w9[cw];
                        dp4a(ds[0][0][0], a4.x, bw00); dp4a(ds[0][0][1], a4.x, bw01);
                        dp4a(ds[0][0][2], a4.y, bw00); dp4a(ds[0][0][3], a4.y, bw01);
                        dp4a(ds[0][1][0], a4.x, bw10); dp4a(ds[0][1][1], a4.x, bw11);
                        dp4a(ds[0][1][2], a4.y, bw10); dp4a(ds[0][1][3], a4.y, bw11);
                        dp4a(ds[1][0][0], a4.z, bw00); dp4a(ds[1][0][1], a4.z, bw01);
                        dp4a(ds[1][0][2], a4.w, bw00); dp4a(ds[1][0][3], a4.w, bw01);
                        dp4a(ds[1][1][0], a4.z, bw10); dp4a(ds[1][1][1], a4.z, bw11);
                        dp4a(ds[1][1][2], a4.w, bw10); dp4a(ds[1][1][3], a4.w, bw11);
                    }
                }
            }

            // ---- fma: conv1(t+1) chunk, cin = {2*koff, 2*koff+1} ----
            if (doc1 && koff < 6) {
#pragma unroll
                for (int ci = 0; ci < 2; ++ci) {
                    const int cin = 2 * koff + ci;
                    const float* xr = xnb + cin * 80 + jb + 2;
                    u64 pv[15];
#pragma unroll
                    for (int m = 0; m < 15; ++m) {
                        float xv = xr[m];
                        pv[m] = pack2(xv, xv);
                    }
#pragma unroll
                    for (int k = 0; k < 7; ++k) {
                        float2 wp = ws1[(cin * 7 + k) * 32 + lane];
                        u64 wpk = pack2(wp.x, wp.y);
#pragma unroll
                        for (int r = 0; r < 9; ++r)
                            ffma2(c1acc[r], pv[r + k], wpk);
                    }
                }
            }
        }

        // ---- spike store for t+1 ----
        if (doc1) {
#pragma unroll
            for (int r = 0; r < 9; ++r) {
                int j = jb + r;
                int l = l0 - 3 + j;
                float v0, v1;
                unpack2(c1acc[r], v0, v1);
                bool in = ((unsigned)l < (unsigned)LEN_);
                unsigned s0 = (in && 2.f * (v0 + b1lo) >= 0.5f) ? 1u : 0u;
                unsigned s1 = (in && 2.f * (v1 + b1hi) >= 0.5f) ? 1u : 0u;
                *reinterpret_cast<unsigned short*>(sptn + j * SPT_PITCH + 2 * lane) =
                    (unsigned short)(s0 | (s1 << 8));
            }
        }

        sts_xs(stg, xs[t & 1]);

        // ---- LIF2: q = (hi<<8) + lo(IMMA h0) + lo(dp4a h1), exact integer ----
#pragma unroll
        for (int mt = 0; mt < 2; ++mt)
#pragma unroll
            for (int nt = 0; nt < 2; ++nt)
#pragma unroll
                for (int e = 0; e < 4; ++e) {
                    int hf = e >> 1;
                    int q = dl[mt][nt][e] + ds[mt][nt][e] + (dh[mt][nt][e] << 8);
                    float hval = fmaf((float)q, SCALE, bb[mt][hf]);
                    float vv = v[mt][nt][e];
                    vv = fmaf(hval - vv, INV_TAU, vv);
                    if (vv >= 0.5f) { accs[mt][hf] += 1.f; vv = 0.f; }
                    v[mt][nt][e] = vv;
                }

        __syncthreads();
    }

#pragma unroll
    for (int mt = 0; mt < 2; ++mt)
#pragma unroll
        for (int hf = 0; hf < 2; ++hf) {
            int c2 = c2h * 64 + wy * 32 + mt * 16 + g + hf * 8;
            atomicAdd(&g_pool[b * C2_ + c2], accs[mt][hf]);
        }
}

// ============================================================================
// Kernel E: FC
// ============================================================================
__global__ void fc_kernel(const float* __restrict__ fcw,
                          const float* __restrict__ fcb,
                          float* __restrict__ out) {
    const int tid = threadIdx.x;
    if (tid < B_ * 4) {
        int b = tid >> 2, n = tid & 3;
        float s = 0.f;
#pragma unroll 8
        for (int c = 0; c < C2_; ++c)
            s += g_pool[b * C2_ + c] * fcw[n * C2_ + c];
        out[b * 4 + n] = s * (1.f / (float)(TT_ * LEN_)) + fcb[n];
    }
}

// ============================================================================
extern "C" void kernel_launch(void* const* d_in, const int* in_sizes, int n_in,
                              void* d_out, int out_size) {
    const float* x   = (const float*)d_in[0];
    const float* w1  = (const float*)d_in[1];
    const float* b1  = (const float*)d_in[2];
    const float* w2  = (const float*)d_in[3];
    const float* b2  = (const float*)d_in[4];
    const float* fcw = (const float*)d_in[5];
    const float* fcb = (const float*)d_in[6];
    float* out = (float*)d_out;

    cudaFuncSetAttribute(fused_kernel,
                         cudaFuncAttributeMaxDynamicSharedMemorySize, SMEM_SZ);

    w2prep_kernel<<<28, 256>>>(w2);                                             // 1
    transpose_kernel<<<dim3(TT_ / 32, LEN_ / 32, B_ * CIN_), dim3(32, 8)>>>(x); // 2
    w1prep_kernel<<<16, 256>>>(w1);                                             // 3
    fused_kernel<<<dim3(16, 2, B_), 256, SMEM_SZ>>>(b1, b2);                    // 4 <- ncu
    fc_kernel<<<1, 128>>>(fcw, fcb, out);                                       // 5
}